// round 6
// baseline (speedup 1.0000x reference)
#include <cuda_runtime.h>
#include <math.h>

#define C      128
#define NPTS   32768
#define KP     20
#define EPSF   1e-7f
#define TPB    256
#define ITER   16
#define NBPC   8            // blocks per channel in k_main: 8*256*16 = 32768
#define NBLK   (C*NBPC)     // 1024

// ---------------- constant-bank weights ----------------
__constant__ float cWx1[64], cbx1[8],  cWx2[8],  cbx2[1];
__constant__ float cWe1[64], cbe1[8],  cWe2[8],  cbe2[1];
__constant__ float cWf1[64], cbf1[8],  cWf2[160], cbf2[20];

// ---------------- device scratch (no allocations allowed) ----------------
__device__ float g_xs[C * NPTS];
__device__ float g_es[C * NPTS];
__device__ float g_yp[C * KP];
__device__ float g_pmin[NBLK], g_pmax[NBLK], g_psum[NBLK], g_psum2[NBLK];
__device__ float g_minv[C], g_invr[C];
__device__ float g_mean, g_scale;

// fast tanh: (e^{2x}-1)/(e^{2x}+1), abs err ~1e-7
__device__ __forceinline__ float ftanh(float x) {
    float xc = fminf(fmaxf(x, -15.f), 15.f);
    float t  = __expf(2.f * xc);
    return __fdividef(t - 1.f, t + 1.f);
}

// ---------------- kernel 1: yp (pts MLP + sort + direction) ----------------
__global__ void k_yp(const float* __restrict__ zf,
                     const unsigned char* __restrict__ dirraw) {
    int c = threadIdx.x;          // 128 threads
    __shared__ int s_isbool;
    if (c == 0) {
        // If directions were serialized as int32, every byte at index %4 != 0
        // is zero. If serialized as bool bytes, random 0/1 appear everywhere.
        int f = 0;
        for (int i = 0; i < 128; i++) if (i & 3) f |= dirraw[i];
        s_isbool = (f != 0);
    }
    __syncthreads();
    if (c >= C) return;

    float z[8];
#pragma unroll
    for (int i = 0; i < 8; i++) z[i] = zf[c * 8 + i];

    float h[8];
#pragma unroll
    for (int j = 0; j < 8; j++) {
        float a = cbf1[j];
#pragma unroll
        for (int k = 0; k < 8; k++) a = fmaf(z[k], cWf1[k * 8 + j], a);
        h[j] = tanhf(a);
    }
    float p[KP];
#pragma unroll
    for (int j = 0; j < KP; j++) {
        float a = cbf2[j];
#pragma unroll
        for (int k = 0; k < 8; k++) a = fmaf(h[k], cWf2[k * 20 + j], a);
        p[j] = tanhf(a);
    }
    // insertion sort ascending (20 elements)
    for (int i = 1; i < KP; i++) {
        float key = p[i];
        int j = i - 1;
        while (j >= 0 && p[j] > key) { p[j + 1] = p[j]; j--; }
        p[j + 1] = key;
    }
    bool d = s_isbool ? (dirraw[c] != 0)
                      : (((const int*)dirraw)[c] != 0);
    for (int j = 0; j < KP; j++)
        g_yp[c * KP + j] = d ? p[j] : p[KP - 1 - j];
}

// ---------------- kernel 2: main MLPs + partial reductions ----------------
__device__ __forceinline__ float mlp_x(const float zv[8]) {
    float acc = cbx2[0];
#pragma unroll
    for (int j = 0; j < 8; j++) {
        float hh = cbx1[j];
#pragma unroll
        for (int k = 0; k < 8; k++) hh = fmaf(zv[k], cWx1[k * 8 + j], hh);
        acc = fmaf(ftanh(hh), cWx2[j], acc);
    }
    return ftanh(acc);
}
__device__ __forceinline__ float mlp_e(const float zv[8]) {
    float acc = cbe2[0];
#pragma unroll
    for (int j = 0; j < 8; j++) {
        float hh = cbe1[j];
#pragma unroll
        for (int k = 0; k < 8; k++) hh = fmaf(zv[k], cWe1[k * 8 + j], hh);
        acc = fmaf(ftanh(hh), cWe2[j], acc);
    }
    return ftanh(acc);
}

__global__ __launch_bounds__(TPB) void k_main(const float* __restrict__ zx,
                                              const float* __restrict__ ze) {
    int c    = blockIdx.y;
    int base = blockIdx.x * (TPB * ITER) + threadIdx.x;
    int row  = c * NPTS;
    const float4* zx4 = (const float4*)zx;
    const float4* ze4 = (const float4*)ze;

    float mn = 1e30f, mx = -1e30f, s = 0.f, s2 = 0.f;

#pragma unroll 2
    for (int k = 0; k < ITER; k++) {
        int n   = base + k * TPB;
        int idx = row + n;

        float4 a = zx4[idx * 2], b = zx4[idx * 2 + 1];
        float zv[8] = {a.x, a.y, a.z, a.w, b.x, b.y, b.z, b.w};
        float xv = mlp_x(zv);
        g_xs[idx] = xv;
        mn = fminf(mn, xv);
        mx = fmaxf(mx, xv);

        a = ze4[idx * 2]; b = ze4[idx * 2 + 1];
        float wv[8] = {a.x, a.y, a.z, a.w, b.x, b.y, b.z, b.w};
        float ev = mlp_e(wv);
        g_es[idx] = ev;
        s += ev;
        s2 = fmaf(ev, ev, s2);
    }

    // deterministic block reduction
    unsigned lane = threadIdx.x & 31u, warp = threadIdx.x >> 5;
#pragma unroll
    for (int off = 16; off; off >>= 1) {
        mn = fminf(mn, __shfl_down_sync(0xffffffffu, mn, off));
        mx = fmaxf(mx, __shfl_down_sync(0xffffffffu, mx, off));
        s  += __shfl_down_sync(0xffffffffu, s,  off);
        s2 += __shfl_down_sync(0xffffffffu, s2, off);
    }
    __shared__ float smn[8], smx[8], ss[8], ss2[8];
    if (lane == 0) { smn[warp] = mn; smx[warp] = mx; ss[warp] = s; ss2[warp] = s2; }
    __syncthreads();
    if (threadIdx.x == 0) {
        mn = smn[0]; mx = smx[0]; s = ss[0]; s2 = ss2[0];
#pragma unroll
        for (int w = 1; w < 8; w++) {
            mn = fminf(mn, smn[w]); mx = fmaxf(mx, smx[w]);
            s += ss[w]; s2 += ss2[w];
        }
        int pb = blockIdx.y * gridDim.x + blockIdx.x;   // c*NBPC + blk
        g_pmin[pb] = mn; g_pmax[pb] = mx;
        g_psum[pb] = s;  g_psum2[pb] = s2;
    }
}

// ---------------- kernel 3: finalize stats ----------------
__global__ void k_stats() {
    int t = threadIdx.x;   // 256 threads, 1 block
    if (t < C) {
        float mn = 1e30f, mx = -1e30f;
#pragma unroll
        for (int i = 0; i < NBPC; i++) {
            mn = fminf(mn, g_pmin[t * NBPC + i]);
            mx = fmaxf(mx, g_pmax[t * NBPC + i]);
        }
        g_minv[t] = mn;
        g_invr[t] = 1.f / (mx - mn);
    }
    float s = 0.f, s2 = 0.f;
    for (int i = t; i < NBLK; i += blockDim.x) { s += g_psum[i]; s2 += g_psum2[i]; }
#pragma unroll
    for (int off = 16; off; off >>= 1) {
        s  += __shfl_down_sync(0xffffffffu, s,  off);
        s2 += __shfl_down_sync(0xffffffffu, s2, off);
    }
    __shared__ float rs[8], rs2[8];
    if ((t & 31) == 0) { rs[t >> 5] = s; rs2[t >> 5] = s2; }
    __syncthreads();
    if (t == 0) {
        double S = 0.0, S2 = 0.0;
        for (int w = 0; w < 8; w++) { S += rs[w]; S2 += rs2[w]; }
        double M    = (double)C * (double)NPTS;
        double mean = S / M;
        double var  = (S2 - S * S / M) / (M - 1.0);
        g_mean  = (float)mean;
        g_scale = (float)(0.1 / sqrt(var));
    }
}

// ---------------- kernel 4: calibrate + noise, [C,N]->[N,C] transpose ----------------
__global__ __launch_bounds__(TPB) void k_final(float* __restrict__ y) {
    __shared__ float s_yp[C * KP];
    __shared__ float s_min[C], s_inv[C];
    __shared__ float sx[C][33];
    __shared__ float se[C][33];

    int tid = threadIdx.x;
    for (int i = tid; i < C * KP; i += TPB) s_yp[i] = g_yp[i];
    if (tid < C) { s_min[tid] = g_minv[tid]; s_inv[tid] = g_invr[tid]; }

    int n0 = blockIdx.x * 32;
    int warp = tid >> 5, lane = tid & 31;
#pragma unroll
    for (int c = warp; c < C; c += 8) {
        sx[c][lane] = g_xs[c * NPTS + n0 + lane];
        se[c][lane] = g_es[c * NPTS + n0 + lane];
    }
    __syncthreads();

    float mean  = g_mean, scale = g_scale;
    const float step = 1.0f / 19.0f;
    const float rden = 1.0f / (step + EPSF);

    int c  = tid & (C - 1);
    int nh = tid >> 7;        // 0 or 1
#pragma unroll
    for (int p = 0; p < 16; p++) {
        int nl = p * 2 + nh;
        float xv = (sx[c][nl] - s_min[c]) * s_inv[c];
        int seg = (int)ceilf(xv * 19.0f) - 1;
        seg = max(0, min(18, seg));
        float y0 = s_yp[c * KP + seg];
        float y1 = s_yp[c * KP + seg + 1];
        float val = fmaf((xv - (float)seg * step) * rden, y1 - y0, y0);
        y[(n0 + nl) * C + c] = fmaf(se[c][nl] - mean, scale, val);
    }
}

// ---------------- launch ----------------
extern "C" void kernel_launch(void* const* d_in, const int* in_sizes, int n_in,
                              void* d_out, int out_size) {
    const float* zf = (const float*)d_in[0];
    const float* zx = (const float*)d_in[1];
    const float* ze = (const float*)d_in[2];

    cudaMemcpyToSymbolAsync(cWx1, d_in[3],  64 * 4, 0, cudaMemcpyDeviceToDevice, 0);
    cudaMemcpyToSymbolAsync(cbx1, d_in[4],   8 * 4, 0, cudaMemcpyDeviceToDevice, 0);
    cudaMemcpyToSymbolAsync(cWx2, d_in[5],   8 * 4, 0, cudaMemcpyDeviceToDevice, 0);
    cudaMemcpyToSymbolAsync(cbx2, d_in[6],   1 * 4, 0, cudaMemcpyDeviceToDevice, 0);
    cudaMemcpyToSymbolAsync(cWe1, d_in[7],  64 * 4, 0, cudaMemcpyDeviceToDevice, 0);
    cudaMemcpyToSymbolAsync(cbe1, d_in[8],   8 * 4, 0, cudaMemcpyDeviceToDevice, 0);
    cudaMemcpyToSymbolAsync(cWe2, d_in[9],   8 * 4, 0, cudaMemcpyDeviceToDevice, 0);
    cudaMemcpyToSymbolAsync(cbe2, d_in[10],  1 * 4, 0, cudaMemcpyDeviceToDevice, 0);
    cudaMemcpyToSymbolAsync(cWf1, d_in[11], 64 * 4, 0, cudaMemcpyDeviceToDevice, 0);
    cudaMemcpyToSymbolAsync(cbf1, d_in[12],  8 * 4, 0, cudaMemcpyDeviceToDevice, 0);
    cudaMemcpyToSymbolAsync(cWf2, d_in[13], 160 * 4, 0, cudaMemcpyDeviceToDevice, 0);
    cudaMemcpyToSymbolAsync(cbf2, d_in[14], 20 * 4, 0, cudaMemcpyDeviceToDevice, 0);

    const unsigned char* dirs = (const unsigned char*)d_in[15];

    k_yp<<<1, 128>>>(zf, dirs);
    dim3 g2(NBPC, C);
    k_main<<<g2, TPB>>>(zx, ze);
    k_stats<<<1, 256>>>();
    k_final<<<NPTS / 32, TPB>>>((float*)d_out);
}

// round 7
// speedup vs baseline: 1.1042x; 1.1042x over previous
#include <cuda_runtime.h>
#include <math.h>

#define C      128
#define NPTS   32768
#define KP     20
#define EPSF   1e-7f
#define TPB    256
#define ITER   16
#define NBPC   8            // blocks per channel: 8*256*16 = 32768
#define NBLK   (C*NBPC)     // 1024

typedef unsigned long long ull;

// ---------------- device scratch (no allocations allowed) ----------------
__device__ float g_xs[C * NPTS];
__device__ float g_es[C * NPTS];
__device__ float g_yp[C * KP];
__device__ float g_pmin[NBLK], g_pmax[NBLK], g_psum[NBLK], g_psum2[NBLK];
__device__ float g_minv[C], g_invr[C];
__device__ float g_mean, g_scale;

// ---------------- packed f32x2 helpers ----------------
__device__ __forceinline__ ull pack2(float x, float y) {
    ull r; asm("mov.b64 %0, {%1, %2};" : "=l"(r) : "f"(x), "f"(y)); return r;
}
__device__ __forceinline__ void unpack2(ull a, float& x, float& y) {
    asm("mov.b64 {%0, %1}, %2;" : "=f"(x), "=f"(y) : "l"(a));
}
__device__ __forceinline__ ull fma2(ull a, ull b, ull c) {
    ull d; asm("fma.rn.f32x2 %0, %1, %2, %3;" : "=l"(d) : "l"(a), "l"(b), "l"(c)); return d;
}
__device__ __forceinline__ ull mul2(ull a, ull b) {
    ull d; asm("mul.rn.f32x2 %0, %1, %2;" : "=l"(d) : "l"(a), "l"(b)); return d;
}
__device__ __forceinline__ float ex2f(float x) {
    float r; asm("ex2.approx.f32 %0, %1;" : "=f"(r) : "f"(x)); return r;
}
__device__ __forceinline__ float rcpf(float x) {
    float r; asm("rcp.approx.f32 %0, %1;" : "=f"(r) : "f"(x)); return r;
}

// tanh(x) = 1 - 2/(1+e^{2x});  e^{2x} = 2^{x*2log2(e)}.  No clamp needed:
// ex2->inf => rcp->0 => 1 ; ex2->0 => rcp(1)=1 => -1.
#define K2LOG2E 2.885390081777927f
__device__ __forceinline__ float tanh1(float x) {
    float t = ex2f(x * K2LOG2E);
    float r = rcpf(t + 1.0f);
    return fmaf(-2.0f, r, 1.0f);
}
// packed tanh: packed front-mul, scalar MUFU back end, repacked result
__device__ __forceinline__ ull tanh2(ull a, ull k2p) {
    ull m = mul2(a, k2p);
    float m0, m1; unpack2(m, m0, m1);
    float t0 = ex2f(m0), t1 = ex2f(m1);
    float r0 = rcpf(t0 + 1.0f), r1 = rcpf(t1 + 1.0f);
    return pack2(fmaf(-2.0f, r0, 1.0f), fmaf(-2.0f, r1, 1.0f));
}

// ---------------- kernel 1: yp (pts MLP + sort + direction) ----------------
__global__ void k_yp(const float* __restrict__ zf,
                     const unsigned char* __restrict__ dirraw,
                     const float* __restrict__ Wf1, const float* __restrict__ bf1,
                     const float* __restrict__ Wf2, const float* __restrict__ bf2) {
    int c = threadIdx.x;          // 128 threads
    __shared__ int s_isbool;
    if (c == 0) {
        // bool-bytes vs int32 storage: int32 has zero bytes at idx%4!=0
        int f = 0;
        for (int i = 0; i < 128; i++) if (i & 3) f |= dirraw[i];
        s_isbool = (f != 0);
    }
    __syncthreads();
    if (c >= C) return;

    float z[8];
#pragma unroll
    for (int i = 0; i < 8; i++) z[i] = zf[c * 8 + i];

    float h[8];
#pragma unroll
    for (int j = 0; j < 8; j++) {
        float a = bf1[j];
#pragma unroll
        for (int k = 0; k < 8; k++) a = fmaf(z[k], Wf1[k * 8 + j], a);
        h[j] = tanhf(a);
    }
    float p[KP];
#pragma unroll
    for (int j = 0; j < KP; j++) {
        float a = bf2[j];
#pragma unroll
        for (int k = 0; k < 8; k++) a = fmaf(h[k], Wf2[k * 20 + j], a);
        p[j] = tanhf(a);
    }
    for (int i = 1; i < KP; i++) {           // insertion sort ascending
        float key = p[i];
        int j = i - 1;
        while (j >= 0 && p[j] > key) { p[j + 1] = p[j]; j--; }
        p[j + 1] = key;
    }
    bool d = s_isbool ? (dirraw[c] != 0) : (((const int*)dirraw)[c] != 0);
    for (int j = 0; j < KP; j++)
        g_yp[c * KP + j] = d ? p[j] : p[KP - 1 - j];
}

// ---------------- packed 8->8->1 tanh MLP (weights in registers) ----------------
__device__ __forceinline__ float mlp_packed(const float z[8],
                                            const ull w1p[32], const ull b1p[4],
                                            const ull w2p[4], float b2s, ull k2p) {
    ull acc0 = b1p[0], acc1 = b1p[1], acc2 = b1p[2], acc3 = b1p[3];
#pragma unroll
    for (int k = 0; k < 8; k++) {
        ull zb = pack2(z[k], z[k]);
        acc0 = fma2(zb, w1p[k * 4 + 0], acc0);
        acc1 = fma2(zb, w1p[k * 4 + 1], acc1);
        acc2 = fma2(zb, w1p[k * 4 + 2], acc2);
        acc3 = fma2(zb, w1p[k * 4 + 3], acc3);
    }
    ull t0 = tanh2(acc0, k2p);
    ull t1 = tanh2(acc1, k2p);
    ull t2 = tanh2(acc2, k2p);
    ull t3 = tanh2(acc3, k2p);
    ull pacc = pack2(b2s, 0.0f);
    pacc = fma2(t0, w2p[0], pacc);
    pacc = fma2(t1, w2p[1], pacc);
    pacc = fma2(t2, w2p[2], pacc);
    pacc = fma2(t3, w2p[3], pacc);
    float lo, hi; unpack2(pacc, lo, hi);
    return tanh1(lo + hi);
}

// ---------------- kernel 2a: x-MLP + per-channel min/max partials ----------------
__global__ __launch_bounds__(TPB, 2) void k_x(const float* __restrict__ zx,
                                              const float* __restrict__ W1,
                                              const float* __restrict__ b1,
                                              const float* __restrict__ W2,
                                              const float* __restrict__ b2) {
    ull w1p[32], b1p[4], w2p[4];
#pragma unroll
    for (int i = 0; i < 32; i++) w1p[i] = ((const ull*)W1)[i];
#pragma unroll
    for (int i = 0; i < 4; i++)  b1p[i] = ((const ull*)b1)[i];
#pragma unroll
    for (int i = 0; i < 4; i++)  w2p[i] = ((const ull*)W2)[i];
    float b2s = b2[0];
    ull k2p = pack2(K2LOG2E, K2LOG2E);

    int c    = blockIdx.y;
    int base = blockIdx.x * (TPB * ITER) + threadIdx.x;
    int row  = c * NPTS;
    const float4* zx4 = (const float4*)zx;

    float mn = 1e30f, mx = -1e30f;

#pragma unroll 2
    for (int k = 0; k < ITER; k++) {
        int idx = row + base + k * TPB;
        float4 a = zx4[idx * 2], b = zx4[idx * 2 + 1];
        float z[8] = {a.x, a.y, a.z, a.w, b.x, b.y, b.z, b.w};
        float xv = mlp_packed(z, w1p, b1p, w2p, b2s, k2p);
        g_xs[idx] = xv;
        mn = fminf(mn, xv);
        mx = fmaxf(mx, xv);
    }

    unsigned lane = threadIdx.x & 31u, warp = threadIdx.x >> 5;
#pragma unroll
    for (int off = 16; off; off >>= 1) {
        mn = fminf(mn, __shfl_down_sync(0xffffffffu, mn, off));
        mx = fmaxf(mx, __shfl_down_sync(0xffffffffu, mx, off));
    }
    __shared__ float smn[8], smx[8];
    if (lane == 0) { smn[warp] = mn; smx[warp] = mx; }
    __syncthreads();
    if (threadIdx.x == 0) {
        mn = smn[0]; mx = smx[0];
#pragma unroll
        for (int w = 1; w < 8; w++) { mn = fminf(mn, smn[w]); mx = fmaxf(mx, smx[w]); }
        int pb = blockIdx.y * gridDim.x + blockIdx.x;
        g_pmin[pb] = mn; g_pmax[pb] = mx;
    }
}

// ---------------- kernel 2b: e-MLP + global sum/sumsq partials ----------------
__global__ __launch_bounds__(TPB, 2) void k_e(const float* __restrict__ ze,
                                              const float* __restrict__ W1,
                                              const float* __restrict__ b1,
                                              const float* __restrict__ W2,
                                              const float* __restrict__ b2) {
    ull w1p[32], b1p[4], w2p[4];
#pragma unroll
    for (int i = 0; i < 32; i++) w1p[i] = ((const ull*)W1)[i];
#pragma unroll
    for (int i = 0; i < 4; i++)  b1p[i] = ((const ull*)b1)[i];
#pragma unroll
    for (int i = 0; i < 4; i++)  w2p[i] = ((const ull*)W2)[i];
    float b2s = b2[0];
    ull k2p = pack2(K2LOG2E, K2LOG2E);

    int c    = blockIdx.y;
    int base = blockIdx.x * (TPB * ITER) + threadIdx.x;
    int row  = c * NPTS;
    const float4* ze4 = (const float4*)ze;

    float s = 0.f, s2 = 0.f;

#pragma unroll 2
    for (int k = 0; k < ITER; k++) {
        int idx = row + base + k * TPB;
        float4 a = ze4[idx * 2], b = ze4[idx * 2 + 1];
        float z[8] = {a.x, a.y, a.z, a.w, b.x, b.y, b.z, b.w};
        float ev = mlp_packed(z, w1p, b1p, w2p, b2s, k2p);
        g_es[idx] = ev;
        s += ev;
        s2 = fmaf(ev, ev, s2);
    }

    unsigned lane = threadIdx.x & 31u, warp = threadIdx.x >> 5;
#pragma unroll
    for (int off = 16; off; off >>= 1) {
        s  += __shfl_down_sync(0xffffffffu, s,  off);
        s2 += __shfl_down_sync(0xffffffffu, s2, off);
    }
    __shared__ float ss[8], ss2[8];
    if (lane == 0) { ss[warp] = s; ss2[warp] = s2; }
    __syncthreads();
    if (threadIdx.x == 0) {
        s = ss[0]; s2 = ss2[0];
#pragma unroll
        for (int w = 1; w < 8; w++) { s += ss[w]; s2 += ss2[w]; }
        int pb = blockIdx.y * gridDim.x + blockIdx.x;
        g_psum[pb] = s; g_psum2[pb] = s2;
    }
}

// ---------------- kernel 3: finalize stats ----------------
__global__ void k_stats() {
    int t = threadIdx.x;   // 256 threads, 1 block
    if (t < C) {
        float mn = 1e30f, mx = -1e30f;
#pragma unroll
        for (int i = 0; i < NBPC; i++) {
            mn = fminf(mn, g_pmin[t * NBPC + i]);
            mx = fmaxf(mx, g_pmax[t * NBPC + i]);
        }
        g_minv[t] = mn;
        g_invr[t] = 1.f / (mx - mn);
    }
    float s = 0.f, s2 = 0.f;
    for (int i = t; i < NBLK; i += blockDim.x) { s += g_psum[i]; s2 += g_psum2[i]; }
#pragma unroll
    for (int off = 16; off; off >>= 1) {
        s  += __shfl_down_sync(0xffffffffu, s,  off);
        s2 += __shfl_down_sync(0xffffffffu, s2, off);
    }
    __shared__ float rs[8], rs2[8];
    if ((t & 31) == 0) { rs[t >> 5] = s; rs2[t >> 5] = s2; }
    __syncthreads();
    if (t == 0) {
        double S = 0.0, S2 = 0.0;
        for (int w = 0; w < 8; w++) { S += rs[w]; S2 += rs2[w]; }
        double M    = (double)C * (double)NPTS;
        double mean = S / M;
        double var  = (S2 - S * S / M) / (M - 1.0);
        g_mean  = (float)mean;
        g_scale = (float)(0.1 / sqrt(var));
    }
}

// ---------------- kernel 4: calibrate + noise, [C,N]->[N,C] transpose ----------------
__global__ __launch_bounds__(256) void k_final(float* __restrict__ y) {
    __shared__ float s_yp[C * 21];          // pad row to 21 words (bank spread)
    __shared__ float s_min[C], s_inv[C];
    __shared__ float sx[32][132];           // [n][c], stride 132: float4-aligned rows
    __shared__ float se[32][132];

    int tid = threadIdx.x;
#pragma unroll
    for (int i = tid; i < C * KP; i += 256) {
        int c = i / KP, kk = i - c * KP;
        s_yp[c * 21 + kk] = g_yp[i];
    }
    if (tid < C) { s_min[tid] = g_minv[tid]; s_inv[tid] = g_invr[tid]; }

    int n0 = blockIdx.x * 32;
#pragma unroll
    for (int i = tid; i < C * 32; i += 256) {
        int c = i >> 5, n = i & 31;         // lanes: consecutive n -> coalesced LDG
        sx[n][c] = g_xs[c * NPTS + n0 + n];
        se[n][c] = g_es[c * NPTS + n0 + n];
    }
    __syncthreads();

    float mean = g_mean, scale = g_scale;
    const float step = 1.0f / 19.0f;
    const float rden = 1.0f / (step + EPSF);

    int cq = tid & 31;        // channel quad: c = 4*cq .. 4*cq+3
    int wn = tid >> 5;        // warp id = base n
#pragma unroll
    for (int p = 0; p < 4; p++) {
        int n = wn + p * 8;
        float4 xv4 = *(const float4*)&sx[n][cq * 4];
        float4 ev4 = *(const float4*)&se[n][cq * 4];
        float xs[4] = {xv4.x, xv4.y, xv4.z, xv4.w};
        float es[4] = {ev4.x, ev4.y, ev4.z, ev4.w};
        float os[4];
#pragma unroll
        for (int j = 0; j < 4; j++) {
            int c = cq * 4 + j;
            float xv = (xs[j] - s_min[c]) * s_inv[c];
            int seg = (int)ceilf(xv * 19.0f) - 1;
            seg = max(0, min(18, seg));
            float y0 = s_yp[c * 21 + seg];
            float y1 = s_yp[c * 21 + seg + 1];
            float f  = (xv - (float)seg * step) * rden;
            os[j] = fmaf(es[j] - mean, scale, fmaf(f, y1 - y0, y0));
        }
        float4 o = {os[0], os[1], os[2], os[3]};
        *(float4*)&y[(n0 + n) * C + cq * 4] = o;
    }
}

// ---------------- launch ----------------
extern "C" void kernel_launch(void* const* d_in, const int* in_sizes, int n_in,
                              void* d_out, int out_size) {
    const float* zf  = (const float*)d_in[0];
    const float* zx  = (const float*)d_in[1];
    const float* ze  = (const float*)d_in[2];
    const float* Wx1 = (const float*)d_in[3];
    const float* bx1 = (const float*)d_in[4];
    const float* Wx2 = (const float*)d_in[5];
    const float* bx2 = (const float*)d_in[6];
    const float* We1 = (const float*)d_in[7];
    const float* be1 = (const float*)d_in[8];
    const float* We2 = (const float*)d_in[9];
    const float* be2 = (const float*)d_in[10];
    const float* Wf1 = (const float*)d_in[11];
    const float* bf1 = (const float*)d_in[12];
    const float* Wf2 = (const float*)d_in[13];
    const float* bf2 = (const float*)d_in[14];
    const unsigned char* dirs = (const unsigned char*)d_in[15];

    k_yp<<<1, 128>>>(zf, dirs, Wf1, bf1, Wf2, bf2);
    dim3 g2(NBPC, C);
    k_x<<<g2, TPB>>>(zx, Wx1, bx1, Wx2, bx2);
    k_e<<<g2, TPB>>>(ze, We1, be1, We2, be2);
    k_stats<<<1, 256>>>();
    k_final<<<NPTS / 32, 256>>>((float*)d_out);
}